// round 4
// baseline (speedup 1.0000x reference)
#include <cuda_runtime.h>

// Problem constants (fixed by the reference setup)
#define S1   32      // patches per image side (256/8)
#define LTOK 320     // tokens per patch problem: N * ip * ip = 5*64
#define NN   5
#define IP   8
#define HH   256
#define MID  2       // N//2
#define NBLK (S1*S1) // 1024

__device__ float g_mid_acc;
__device__ float g_all_acc;
__device__ float g_rec_acc;

__global__ void init_kernel() {
    g_mid_acc = 0.0f;
    g_all_acc = 0.0f;
    g_rec_acc = 0.0f;
}

__global__ void __launch_bounds__(LTOK) attn_loss_kernel(
    const float* __restrict__ inp,     // (1,5,3,256,256)
    const float* __restrict__ outp,    // (1,5,3,256,256)
    const float* __restrict__ Wq,      // (3,3)
    const float* __restrict__ Wk,      // (3,3)
    const float* __restrict__ bq,      // (3,)
    const float* __restrict__ bk,      // (3,)
    const float* __restrict__ bv,      // (3,)
    float* __restrict__ rec_out)       // d_out + 1, 3*256*256 floats
{
    __shared__ float4 k4[LTOK];
    __shared__ float4 v4[LTOK];
    __shared__ float  outS[LTOK][3];
    __shared__ float  wp[27];          // Wq[0:9] Wk[9:18] bq[18:21] bk[21:24] bv[24:27]
    __shared__ float  red[3];          // block partials: mid, all, rec

    const int t  = threadIdx.x;
    const int r  = blockIdx.x;
    const int r1 = r >> 5;             // patch row
    const int r2 = r & 31;             // patch col

    if (t < 9)       wp[t] = Wq[t];
    else if (t < 18) wp[t] = Wk[t - 9];
    else if (t < 21) wp[t] = bq[t - 18];
    else if (t < 24) wp[t] = bk[t - 21];
    else if (t < 27) wp[t] = bv[t - 24];
    if (t == 0) { red[0] = 0.f; red[1] = 0.f; red[2] = 0.f; }
    __syncthreads();

    // ---- load this thread's token (row l = t) and build q, k, v ----
    // l = n*64 + ph*8 + pw ; pixel = (r1*8+ph, r2*8+pw)
    const int n  = t >> 6;
    const int pp = t & 63;
    const int h  = r1 * IP + (pp >> 3);
    const int w  = r2 * IP + (pp & 7);
    const int base = ((n * 3) * HH + h) * HH + w;
    const float x0 = inp[base];
    const float x1 = inp[base + HH * HH];
    const float x2 = inp[base + 2 * HH * HH];

    const float inv_sqrt3 = 0.5773502691896258f;
    const float q0 = (wp[0] * x0 + wp[1] * x1 + wp[2] * x2 + wp[18]) * inv_sqrt3;
    const float q1 = (wp[3] * x0 + wp[4] * x1 + wp[5] * x2 + wp[19]) * inv_sqrt3;
    const float q2 = (wp[6] * x0 + wp[7] * x1 + wp[8] * x2 + wp[20]) * inv_sqrt3;

    const float kk0 = wp[9]  * x0 + wp[10] * x1 + wp[11] * x2 + wp[21];
    const float kk1 = wp[12] * x0 + wp[13] * x1 + wp[14] * x2 + wp[22];
    const float kk2 = wp[15] * x0 + wp[16] * x1 + wp[17] * x2 + wp[23];

    k4[t] = make_float4(kk0, kk1, kk2, 0.f);
    v4[t] = make_float4(x0 + wp[24], x1 + wp[25], x2 + wp[26], 0.f);
    __syncthreads();

    // ---- streaming softmax-attention for query t ----
    // No max subtraction: scores bounded, fp32 exp is safe; mathematically
    // identical to jax's max-subtracted softmax.
    float se = 0.f, a0 = 0.f, a1 = 0.f, a2 = 0.f;
#pragma unroll 4
    for (int m = 0; m < LTOK; m++) {
        const float4 kv = k4[m];
        const float sc = q0 * kv.x + q1 * kv.y + q2 * kv.z;
        const float e  = __expf(sc);
        const float4 vv = v4[m];
        se += e;
        a0 += e * vv.x;
        a1 += e * vv.y;
        a2 += e * vv.z;
    }
    const float inv = 1.0f / se;
    outS[t][0] = a0 * inv;
    outS[t][1] = a1 * inv;
    outS[t][2] = a2 * inv;
    __syncthreads();

    // ---- losses ----
    float lm = 0.f, la = 0.f, lr = 0.f;

    // all_loss / mid_loss: 960 elements (n,c,ph,pw), 3 per thread
#pragma unroll
    for (int i = 0; i < 3; i++) {
        const int e   = t + i * LTOK;
        const int n2  = e / 192;
        const int rem = e - n2 * 192;
        const int c   = rem >> 6;
        const int pp2 = rem & 63;
        const int h2  = r1 * IP + (pp2 >> 3);
        const int w2  = r2 * IP + (pp2 & 7);
        const float nin  = outp[((n2 * 3 + c) * HH + h2) * HH + w2];
        const float ninm = outp[((MID * 3 + c) * HH + h2) * HH + w2];
        const float al   = outS[n2 * 64 + pp2][c];
        const float da = nin - al;
        const float dm = ninm - al;
        la += da * da;
        lm += dm * dm;
    }

    // rec (mean over N) + rec_image write + rec_loss partial: 192 elements
    if (t < 192) {
        const int c   = t >> 6;
        const int pp2 = t & 63;
        const int h2  = r1 * IP + (pp2 >> 3);
        const int w2  = r2 * IP + (pp2 & 7);
        const float rec = 0.2f * (outS[pp2][c] + outS[64 + pp2][c] + outS[128 + pp2][c]
                                  + outS[192 + pp2][c] + outS[256 + pp2][c]);
        rec_out[(c * HH + h2) * HH + w2] = rec;
        const float om = outp[((MID * 3 + c) * HH + h2) * HH + w2];
        const float d  = om - rec;
        lr = d * d;
    }

    // warp reduce then block reduce
#pragma unroll
    for (int o = 16; o > 0; o >>= 1) {
        lm += __shfl_down_sync(0xffffffffu, lm, o);
        la += __shfl_down_sync(0xffffffffu, la, o);
        lr += __shfl_down_sync(0xffffffffu, lr, o);
    }
    if ((t & 31) == 0) {
        atomicAdd(&red[0], lm);
        atomicAdd(&red[1], la);
        atomicAdd(&red[2], lr);
    }
    __syncthreads();
    if (t == 0) {
        atomicAdd(&g_mid_acc, red[0] * (1.0f / 960.0f));
        atomicAdd(&g_all_acc, red[1] * (1.0f / 960.0f));
        atomicAdd(&g_rec_acc, red[2]);
    }
}

__global__ void final_kernel(const float* __restrict__ loss_diff,
                             const int* __restrict__ step,
                             const int* __restrict__ max_steps,
                             float* __restrict__ out)
{
    const float frac = 1.0f - (float)step[0] / (float)max_steps[0];
    float p = frac;
    // frac^10 exactly via repeated multiply (matches (0.9)^10 to fp32 rounding)
    float f2 = p * p;           // ^2
    float f4 = f2 * f2;         // ^4
    float f8 = f4 * f4;         // ^8
    float f10 = f8 * f2;        // ^10
    const float coeff = loss_diff[0] * f10;
    out[0] = g_mid_acc + coeff * g_all_acc + g_rec_acc * (1.0f / 196608.0f);
}

extern "C" void kernel_launch(void* const* d_in, const int* in_sizes, int n_in,
                              void* d_out, int out_size)
{
    const float* inp  = (const float*)d_in[0];
    const float* outp = (const float*)d_in[1];
    const float* Wq   = (const float*)d_in[2];
    const float* Wk   = (const float*)d_in[3];
    const float* bq   = (const float*)d_in[4];
    const float* bk   = (const float*)d_in[5];
    const float* bv   = (const float*)d_in[6];
    const float* ld   = (const float*)d_in[7];
    const int*   st   = (const int*)d_in[8];
    const int*   ms   = (const int*)d_in[9];
    float* out = (float*)d_out;

    init_kernel<<<1, 1>>>();
    attn_loss_kernel<<<NBLK, LTOK>>>(inp, outp, Wq, Wk, bq, bk, bv, out + 1);
    final_kernel<<<1, 1>>>(ld, st, ms, out);
}

// round 5
// speedup vs baseline: 1.0015x; 1.0015x over previous
#include <cuda_runtime.h>

// Problem constants (fixed by the reference setup)
#define S1   32      // patches per image side (256/8)
#define LTOK 320     // tokens per patch problem: N * ip * ip = 5*64
#define NN   5
#define IP   8
#define HH   256
#define MID  2       // N//2
#define NBLK (S1*S1) // 1024

__device__ float g_mid_acc;
__device__ float g_all_acc;
__device__ float g_rec_acc;

__global__ void init_kernel() {
    g_mid_acc = 0.0f;
    g_all_acc = 0.0f;
    g_rec_acc = 0.0f;
}

__global__ void __launch_bounds__(LTOK) attn_loss_kernel(
    const float* __restrict__ inp,     // (1,5,3,256,256)
    const float* __restrict__ outp,    // (1,5,3,256,256)
    const float* __restrict__ Wq,      // (3,3)
    const float* __restrict__ Wk,      // (3,3)
    const float* __restrict__ bq,      // (3,)
    const float* __restrict__ bk,      // (3,)
    const float* __restrict__ bv,      // (3,)
    float* __restrict__ rec_out)       // d_out + 1, 3*256*256 floats
{
    __shared__ float4 k4[LTOK];
    __shared__ float4 v4[LTOK];
    __shared__ float  outS[LTOK][3];
    __shared__ float  wp[27];          // Wq[0:9] Wk[9:18] bq[18:21] bk[21:24] bv[24:27]
    __shared__ float  red[3];          // block partials: mid, all, rec

    const int t  = threadIdx.x;
    const int r  = blockIdx.x;
    const int r1 = r >> 5;             // patch row
    const int r2 = r & 31;             // patch col

    if (t < 9)       wp[t] = Wq[t];
    else if (t < 18) wp[t] = Wk[t - 9];
    else if (t < 21) wp[t] = bq[t - 18];
    else if (t < 24) wp[t] = bk[t - 21];
    else if (t < 27) wp[t] = bv[t - 24];
    if (t == 0) { red[0] = 0.f; red[1] = 0.f; red[2] = 0.f; }
    __syncthreads();

    // ---- load this thread's token (row l = t) and build q, k, v ----
    // l = n*64 + ph*8 + pw ; pixel = (r1*8+ph, r2*8+pw)
    const int n  = t >> 6;
    const int pp = t & 63;
    const int h  = r1 * IP + (pp >> 3);
    const int w  = r2 * IP + (pp & 7);
    const int base = ((n * 3) * HH + h) * HH + w;
    const float x0 = inp[base];
    const float x1 = inp[base + HH * HH];
    const float x2 = inp[base + 2 * HH * HH];

    const float inv_sqrt3 = 0.5773502691896258f;
    const float q0 = (wp[0] * x0 + wp[1] * x1 + wp[2] * x2 + wp[18]) * inv_sqrt3;
    const float q1 = (wp[3] * x0 + wp[4] * x1 + wp[5] * x2 + wp[19]) * inv_sqrt3;
    const float q2 = (wp[6] * x0 + wp[7] * x1 + wp[8] * x2 + wp[20]) * inv_sqrt3;

    const float kk0 = wp[9]  * x0 + wp[10] * x1 + wp[11] * x2 + wp[21];
    const float kk1 = wp[12] * x0 + wp[13] * x1 + wp[14] * x2 + wp[22];
    const float kk2 = wp[15] * x0 + wp[16] * x1 + wp[17] * x2 + wp[23];

    k4[t] = make_float4(kk0, kk1, kk2, 0.f);
    v4[t] = make_float4(x0 + wp[24], x1 + wp[25], x2 + wp[26], 0.f);
    __syncthreads();

    // ---- streaming softmax-attention for query t ----
    // No max subtraction: scores bounded, fp32 exp is safe; mathematically
    // identical to jax's max-subtracted softmax.
    float se = 0.f, a0 = 0.f, a1 = 0.f, a2 = 0.f;
#pragma unroll 4
    for (int m = 0; m < LTOK; m++) {
        const float4 kv = k4[m];
        const float sc = q0 * kv.x + q1 * kv.y + q2 * kv.z;
        const float e  = __expf(sc);
        const float4 vv = v4[m];
        se += e;
        a0 += e * vv.x;
        a1 += e * vv.y;
        a2 += e * vv.z;
    }
    const float inv = 1.0f / se;
    outS[t][0] = a0 * inv;
    outS[t][1] = a1 * inv;
    outS[t][2] = a2 * inv;
    __syncthreads();

    // ---- losses ----
    float lm = 0.f, la = 0.f, lr = 0.f;

    // all_loss / mid_loss: 960 elements (n,c,ph,pw), 3 per thread
#pragma unroll
    for (int i = 0; i < 3; i++) {
        const int e   = t + i * LTOK;
        const int n2  = e / 192;
        const int rem = e - n2 * 192;
        const int c   = rem >> 6;
        const int pp2 = rem & 63;
        const int h2  = r1 * IP + (pp2 >> 3);
        const int w2  = r2 * IP + (pp2 & 7);
        const float nin  = outp[((n2 * 3 + c) * HH + h2) * HH + w2];
        const float ninm = outp[((MID * 3 + c) * HH + h2) * HH + w2];
        const float al   = outS[n2 * 64 + pp2][c];
        const float da = nin - al;
        const float dm = ninm - al;
        la += da * da;
        lm += dm * dm;
    }

    // rec (mean over N) + rec_image write + rec_loss partial: 192 elements
    if (t < 192) {
        const int c   = t >> 6;
        const int pp2 = t & 63;
        const int h2  = r1 * IP + (pp2 >> 3);
        const int w2  = r2 * IP + (pp2 & 7);
        const float rec = 0.2f * (outS[pp2][c] + outS[64 + pp2][c] + outS[128 + pp2][c]
                                  + outS[192 + pp2][c] + outS[256 + pp2][c]);
        rec_out[(c * HH + h2) * HH + w2] = rec;
        const float om = outp[((MID * 3 + c) * HH + h2) * HH + w2];
        const float d  = om - rec;
        lr = d * d;
    }

    // warp reduce then block reduce
#pragma unroll
    for (int o = 16; o > 0; o >>= 1) {
        lm += __shfl_down_sync(0xffffffffu, lm, o);
        la += __shfl_down_sync(0xffffffffu, la, o);
        lr += __shfl_down_sync(0xffffffffu, lr, o);
    }
    if ((t & 31) == 0) {
        atomicAdd(&red[0], lm);
        atomicAdd(&red[1], la);
        atomicAdd(&red[2], lr);
    }
    __syncthreads();
    if (t == 0) {
        atomicAdd(&g_mid_acc, red[0] * (1.0f / 960.0f));
        atomicAdd(&g_all_acc, red[1] * (1.0f / 960.0f));
        atomicAdd(&g_rec_acc, red[2]);
    }
}

__global__ void final_kernel(const float* __restrict__ loss_diff,
                             const int* __restrict__ step,
                             const int* __restrict__ max_steps,
                             float* __restrict__ out)
{
    const float frac = 1.0f - (float)step[0] / (float)max_steps[0];
    float p = frac;
    // frac^10 exactly via repeated multiply (matches (0.9)^10 to fp32 rounding)
    float f2 = p * p;           // ^2
    float f4 = f2 * f2;         // ^4
    float f8 = f4 * f4;         // ^8
    float f10 = f8 * f2;        // ^10
    const float coeff = loss_diff[0] * f10;
    out[0] = g_mid_acc + coeff * g_all_acc + g_rec_acc * (1.0f / 196608.0f);
}

extern "C" void kernel_launch(void* const* d_in, const int* in_sizes, int n_in,
                              void* d_out, int out_size)
{
    const float* inp  = (const float*)d_in[0];
    const float* outp = (const float*)d_in[1];
    const float* Wq   = (const float*)d_in[2];
    const float* Wk   = (const float*)d_in[3];
    const float* bq   = (const float*)d_in[4];
    const float* bk   = (const float*)d_in[5];
    const float* bv   = (const float*)d_in[6];
    const float* ld   = (const float*)d_in[7];
    const int*   st   = (const int*)d_in[8];
    const int*   ms   = (const int*)d_in[9];
    float* out = (float*)d_out;

    init_kernel<<<1, 1>>>();
    attn_loss_kernel<<<NBLK, LTOK>>>(inp, outp, Wq, Wk, bq, bk, bv, out + 1);
    final_kernel<<<1, 1>>>(ld, st, ms, out);
}

// round 6
// speedup vs baseline: 1.0145x; 1.0129x over previous
#include <cuda_runtime.h>

// Problem constants (fixed by the reference setup)
#define S1   32      // patches per image side (256/8)
#define LTOK 320     // tokens per patch problem: N * ip * ip = 5*64
#define NN   5
#define IP   8
#define HH   256
#define MID  2       // N//2
#define NBLK (S1*S1) // 1024

__device__ float g_mid_acc;
__device__ float g_all_acc;
__device__ float g_rec_acc;

__global__ void init_kernel() {
    g_mid_acc = 0.0f;
    g_all_acc = 0.0f;
    g_rec_acc = 0.0f;
}

__global__ void __launch_bounds__(LTOK) attn_loss_kernel(
    const float* __restrict__ inp,     // (1,5,3,256,256)
    const float* __restrict__ outp,    // (1,5,3,256,256)
    const float* __restrict__ Wq,      // (3,3)
    const float* __restrict__ Wk,      // (3,3)
    const float* __restrict__ bq,      // (3,)
    const float* __restrict__ bk,      // (3,)
    const float* __restrict__ bv,      // (3,)
    float* __restrict__ rec_out)       // d_out + 1, 3*256*256 floats
{
    __shared__ float4 k4[LTOK];
    __shared__ float4 v4[LTOK];
    __shared__ float  outS[LTOK][3];
    __shared__ float  wp[27];          // Wq[0:9] Wk[9:18] bq[18:21] bk[21:24] bv[24:27]
    __shared__ float  red[3];          // block partials: mid, all, rec

    const int t  = threadIdx.x;
    const int r  = blockIdx.x;
    const int r1 = r >> 5;             // patch row
    const int r2 = r & 31;             // patch col

    if (t < 9)       wp[t] = Wq[t];
    else if (t < 18) wp[t] = Wk[t - 9];
    else if (t < 21) wp[t] = bq[t - 18];
    else if (t < 24) wp[t] = bk[t - 21];
    else if (t < 27) wp[t] = bv[t - 24];
    if (t == 0) { red[0] = 0.f; red[1] = 0.f; red[2] = 0.f; }
    __syncthreads();

    // ---- load this thread's token (row l = t) and build q, k, v ----
    // l = n*64 + ph*8 + pw ; pixel = (r1*8+ph, r2*8+pw)
    const int n  = t >> 6;
    const int pp = t & 63;
    const int h  = r1 * IP + (pp >> 3);
    const int w  = r2 * IP + (pp & 7);
    const int base = ((n * 3) * HH + h) * HH + w;
    const float x0 = inp[base];
    const float x1 = inp[base + HH * HH];
    const float x2 = inp[base + 2 * HH * HH];

    const float inv_sqrt3 = 0.5773502691896258f;
    const float q0 = (wp[0] * x0 + wp[1] * x1 + wp[2] * x2 + wp[18]) * inv_sqrt3;
    const float q1 = (wp[3] * x0 + wp[4] * x1 + wp[5] * x2 + wp[19]) * inv_sqrt3;
    const float q2 = (wp[6] * x0 + wp[7] * x1 + wp[8] * x2 + wp[20]) * inv_sqrt3;

    const float kk0 = wp[9]  * x0 + wp[10] * x1 + wp[11] * x2 + wp[21];
    const float kk1 = wp[12] * x0 + wp[13] * x1 + wp[14] * x2 + wp[22];
    const float kk2 = wp[15] * x0 + wp[16] * x1 + wp[17] * x2 + wp[23];

    k4[t] = make_float4(kk0, kk1, kk2, 0.f);
    v4[t] = make_float4(x0 + wp[24], x1 + wp[25], x2 + wp[26], 0.f);
    __syncthreads();

    // ---- streaming softmax-attention for query t ----
    // No max subtraction: scores bounded, fp32 exp is safe; mathematically
    // identical to jax's max-subtracted softmax.
    float se = 0.f, a0 = 0.f, a1 = 0.f, a2 = 0.f;
#pragma unroll 4
    for (int m = 0; m < LTOK; m++) {
        const float4 kv = k4[m];
        const float sc = q0 * kv.x + q1 * kv.y + q2 * kv.z;
        const float e  = __expf(sc);
        const float4 vv = v4[m];
        se += e;
        a0 += e * vv.x;
        a1 += e * vv.y;
        a2 += e * vv.z;
    }
    const float inv = 1.0f / se;
    outS[t][0] = a0 * inv;
    outS[t][1] = a1 * inv;
    outS[t][2] = a2 * inv;
    __syncthreads();

    // ---- losses ----
    float lm = 0.f, la = 0.f, lr = 0.f;

    // all_loss / mid_loss: 960 elements (n,c,ph,pw), 3 per thread
#pragma unroll
    for (int i = 0; i < 3; i++) {
        const int e   = t + i * LTOK;
        const int n2  = e / 192;
        const int rem = e - n2 * 192;
        const int c   = rem >> 6;
        const int pp2 = rem & 63;
        const int h2  = r1 * IP + (pp2 >> 3);
        const int w2  = r2 * IP + (pp2 & 7);
        const float nin  = outp[((n2 * 3 + c) * HH + h2) * HH + w2];
        const float ninm = outp[((MID * 3 + c) * HH + h2) * HH + w2];
        const float al   = outS[n2 * 64 + pp2][c];
        const float da = nin - al;
        const float dm = ninm - al;
        la += da * da;
        lm += dm * dm;
    }

    // rec (mean over N) + rec_image write + rec_loss partial: 192 elements
    if (t < 192) {
        const int c   = t >> 6;
        const int pp2 = t & 63;
        const int h2  = r1 * IP + (pp2 >> 3);
        const int w2  = r2 * IP + (pp2 & 7);
        const float rec = 0.2f * (outS[pp2][c] + outS[64 + pp2][c] + outS[128 + pp2][c]
                                  + outS[192 + pp2][c] + outS[256 + pp2][c]);
        rec_out[(c * HH + h2) * HH + w2] = rec;
        const float om = outp[((MID * 3 + c) * HH + h2) * HH + w2];
        const float d  = om - rec;
        lr = d * d;
    }

    // warp reduce then block reduce
#pragma unroll
    for (int o = 16; o > 0; o >>= 1) {
        lm += __shfl_down_sync(0xffffffffu, lm, o);
        la += __shfl_down_sync(0xffffffffu, la, o);
        lr += __shfl_down_sync(0xffffffffu, lr, o);
    }
    if ((t & 31) == 0) {
        atomicAdd(&red[0], lm);
        atomicAdd(&red[1], la);
        atomicAdd(&red[2], lr);
    }
    __syncthreads();
    if (t == 0) {
        atomicAdd(&g_mid_acc, red[0] * (1.0f / 960.0f));
        atomicAdd(&g_all_acc, red[1] * (1.0f / 960.0f));
        atomicAdd(&g_rec_acc, red[2]);
    }
}

__global__ void final_kernel(const float* __restrict__ loss_diff,
                             const int* __restrict__ step,
                             const int* __restrict__ max_steps,
                             float* __restrict__ out)
{
    const float frac = 1.0f - (float)step[0] / (float)max_steps[0];
    float p = frac;
    // frac^10 exactly via repeated multiply (matches (0.9)^10 to fp32 rounding)
    float f2 = p * p;           // ^2
    float f4 = f2 * f2;         // ^4
    float f8 = f4 * f4;         // ^8
    float f10 = f8 * f2;        // ^10
    const float coeff = loss_diff[0] * f10;
    out[0] = g_mid_acc + coeff * g_all_acc + g_rec_acc * (1.0f / 196608.0f);
}

extern "C" void kernel_launch(void* const* d_in, const int* in_sizes, int n_in,
                              void* d_out, int out_size)
{
    const float* inp  = (const float*)d_in[0];
    const float* outp = (const float*)d_in[1];
    const float* Wq   = (const float*)d_in[2];
    const float* Wk   = (const float*)d_in[3];
    const float* bq   = (const float*)d_in[4];
    const float* bk   = (const float*)d_in[5];
    const float* bv   = (const float*)d_in[6];
    const float* ld   = (const float*)d_in[7];
    const int*   st   = (const int*)d_in[8];
    const int*   ms   = (const int*)d_in[9];
    float* out = (float*)d_out;

    init_kernel<<<1, 1>>>();
    attn_loss_kernel<<<NBLK, LTOK>>>(inp, outp, Wq, Wk, bq, bk, bv, out + 1);
    final_kernel<<<1, 1>>>(ld, st, ms, out);
}

// round 7
// speedup vs baseline: 1.2253x; 1.2079x over previous
#include <cuda_runtime.h>

// Problem constants (fixed by the reference setup)
#define S1   32      // patches per image side (256/8)
#define LTOK 320     // tokens per patch problem: N * ip * ip = 5*64
#define NPAIR (LTOK/2)
#define NN   5
#define IP   8
#define HH   256
#define MID  2       // N//2
#define NBLK (S1*S1) // 1024

__device__ float g_mid_acc;
__device__ float g_all_acc;
__device__ float g_rec_acc;

// ---------- f32x2 packed-math helpers (Blackwell FFMA2 path, PTX-only) ----------
typedef unsigned long long ull;

__device__ __forceinline__ ull pack2(float lo, float hi) {
    ull r;
    asm("mov.b64 %0, {%1, %2};" : "=l"(r) : "f"(lo), "f"(hi));
    return r;
}
__device__ __forceinline__ void unpack2(ull v, float& lo, float& hi) {
    asm("mov.b64 {%0, %1}, %2;" : "=f"(lo), "=f"(hi) : "l"(v));
}
__device__ __forceinline__ ull fma2(ull a, ull b, ull c) {
    ull d;
    asm("fma.rn.f32x2 %0, %1, %2, %3;" : "=l"(d) : "l"(a), "l"(b), "l"(c));
    return d;
}
__device__ __forceinline__ ull mul2(ull a, ull b) {
    ull d;
    asm("mul.rn.f32x2 %0, %1, %2;" : "=l"(d) : "l"(a), "l"(b));
    return d;
}
__device__ __forceinline__ ull add2(ull a, ull b) {
    ull d;
    asm("add.rn.f32x2 %0, %1, %2;" : "=l"(d) : "l"(a), "l"(b));
    return d;
}
__device__ __forceinline__ float ex2a(float x) {
    float y;
    asm("ex2.approx.ftz.f32 %0, %1;" : "=f"(y) : "f"(x));
    return y;
}

__global__ void __launch_bounds__(LTOK) attn_loss_kernel(
    const float* __restrict__ inp,     // (1,5,3,256,256)
    const float* __restrict__ outp,    // (1,5,3,256,256)
    const float* __restrict__ Wq,      // (3,3)
    const float* __restrict__ Wk,      // (3,3)
    const float* __restrict__ bq,      // (3,)
    const float* __restrict__ bk,      // (3,)
    const float* __restrict__ bv,      // (3,)
    float* __restrict__ rec_out)       // d_out + 1, 3*256*256 floats
{
    // Pair-packed SMEM layout. Pair j = tokens (2j, 2j+1).
    //   A[j] = { kx0,kx1, ky0,ky1 }   (two 64-bit halves: kx-pair, ky-pair)
    //   B[j] = { kz0,kz1, vx0,vx1 }
    //   C[j] = { vy0,vy1, vz0,vz1 }
    __shared__ __align__(16) float A_f[NPAIR * 4];
    __shared__ __align__(16) float B_f[NPAIR * 4];
    __shared__ __align__(16) float C_f[NPAIR * 4];
    __shared__ float  outS[LTOK][3];
    __shared__ float  wp[27];          // Wq[0:9] Wk[9:18] bq[18:21] bk[21:24] bv[24:27]
    __shared__ float  red[3];          // block partials: mid, all, rec

    const int t  = threadIdx.x;
    const int r  = blockIdx.x;
    const int r1 = r >> 5;             // patch row
    const int r2 = r & 31;             // patch col

    if (t < 9)       wp[t] = Wq[t];
    else if (t < 18) wp[t] = Wk[t - 9];
    else if (t < 21) wp[t] = bq[t - 18];
    else if (t < 24) wp[t] = bk[t - 21];
    else if (t < 27) wp[t] = bv[t - 24];
    if (t == 0) { red[0] = 0.f; red[1] = 0.f; red[2] = 0.f; }
    __syncthreads();

    // ---- load this thread's token (row l = t) and build q, k, v ----
    const int n  = t >> 6;
    const int pp = t & 63;
    const int h  = r1 * IP + (pp >> 3);
    const int w  = r2 * IP + (pp & 7);
    const int base = ((n * 3) * HH + h) * HH + w;
    const float x0 = inp[base];
    const float x1 = inp[base + HH * HH];
    const float x2 = inp[base + 2 * HH * HH];

    // q scaled by 1/sqrt(3) AND log2(e): scores computed directly in log2 domain.
    const float qs = 0.5773502691896258f * 1.4426950408889634f;
    const float q0 = (wp[0] * x0 + wp[1] * x1 + wp[2] * x2 + wp[18]) * qs;
    const float q1 = (wp[3] * x0 + wp[4] * x1 + wp[5] * x2 + wp[19]) * qs;
    const float q2 = (wp[6] * x0 + wp[7] * x1 + wp[8] * x2 + wp[20]) * qs;

    const float kk0 = wp[9]  * x0 + wp[10] * x1 + wp[11] * x2 + wp[21];
    const float kk1 = wp[12] * x0 + wp[13] * x1 + wp[14] * x2 + wp[22];
    const float kk2 = wp[15] * x0 + wp[16] * x1 + wp[17] * x2 + wp[23];
    const float vv0 = x0 + wp[24];
    const float vv1 = x1 + wp[25];
    const float vv2 = x2 + wp[26];

    {
        const int j = t >> 1, o = t & 1;
        A_f[4 * j + o]     = kk0;
        A_f[4 * j + 2 + o] = kk1;
        B_f[4 * j + o]     = kk2;
        B_f[4 * j + 2 + o] = vv0;
        C_f[4 * j + o]     = vv1;
        C_f[4 * j + 2 + o] = vv2;
    }
    __syncthreads();

    // ---- streaming softmax-attention for query t, 2 keys per iteration ----
    const ull qx2 = pack2(q0, q0);
    const ull qy2 = pack2(q1, q1);
    const ull qz2 = pack2(q2, q2);

    ull se2 = 0ull, a02 = 0ull, a12 = 0ull, a22 = 0ull;  // (0.f,0.f) bit pattern

    const ulonglong2* __restrict__ A2 = (const ulonglong2*)A_f;
    const ulonglong2* __restrict__ B2 = (const ulonglong2*)B_f;
    const ulonglong2* __restrict__ C2 = (const ulonglong2*)C_f;

#pragma unroll 8
    for (int m = 0; m < NPAIR; m++) {
        const ulonglong2 a = A2[m];                 // kx-pair, ky-pair
        const ulonglong2 b = B2[m];                 // kz-pair, vx-pair
        ull sc = mul2(qx2, a.x);
        sc = fma2(qy2, a.y, sc);
        sc = fma2(qz2, b.x, sc);                    // log2-domain scores
        float slo, shi;
        unpack2(sc, slo, shi);
        const ull e = pack2(ex2a(slo), ex2a(shi));  // exp(score)
        const ulonglong2 c = C2[m];                 // vy-pair, vz-pair
        se2 = add2(se2, e);
        a02 = fma2(e, b.y, a02);
        a12 = fma2(e, c.x, a12);
        a22 = fma2(e, c.y, a22);
    }

    float sA, sB, o0a, o0b, o1a, o1b, o2a, o2b;
    unpack2(se2, sA, sB);
    unpack2(a02, o0a, o0b);
    unpack2(a12, o1a, o1b);
    unpack2(a22, o2a, o2b);
    const float inv = 1.0f / (sA + sB);
    outS[t][0] = (o0a + o0b) * inv;
    outS[t][1] = (o1a + o1b) * inv;
    outS[t][2] = (o2a + o2b) * inv;
    __syncthreads();

    // ---- losses ----
    float lm = 0.f, la = 0.f, lr = 0.f;

    // all_loss / mid_loss: 960 elements (n,c,ph,pw), 3 per thread
#pragma unroll
    for (int i = 0; i < 3; i++) {
        const int e   = t + i * LTOK;
        const int n2  = e / 192;
        const int rem = e - n2 * 192;
        const int c   = rem >> 6;
        const int pp2 = rem & 63;
        const int h2  = r1 * IP + (pp2 >> 3);
        const int w2  = r2 * IP + (pp2 & 7);
        const float nin  = outp[((n2 * 3 + c) * HH + h2) * HH + w2];
        const float ninm = outp[((MID * 3 + c) * HH + h2) * HH + w2];
        const float al   = outS[n2 * 64 + pp2][c];
        const float da = nin - al;
        const float dm = ninm - al;
        la += da * da;
        lm += dm * dm;
    }

    // rec (mean over N) + rec_image write + rec_loss partial: 192 elements
    if (t < 192) {
        const int c   = t >> 6;
        const int pp2 = t & 63;
        const int h2  = r1 * IP + (pp2 >> 3);
        const int w2  = r2 * IP + (pp2 & 7);
        const float rec = 0.2f * (outS[pp2][c] + outS[64 + pp2][c] + outS[128 + pp2][c]
                                  + outS[192 + pp2][c] + outS[256 + pp2][c]);
        rec_out[(c * HH + h2) * HH + w2] = rec;
        const float om = outp[((MID * 3 + c) * HH + h2) * HH + w2];
        const float d  = om - rec;
        lr = d * d;
    }

    // warp reduce then block reduce
#pragma unroll
    for (int o = 16; o > 0; o >>= 1) {
        lm += __shfl_down_sync(0xffffffffu, lm, o);
        la += __shfl_down_sync(0xffffffffu, la, o);
        lr += __shfl_down_sync(0xffffffffu, lr, o);
    }
    if ((t & 31) == 0) {
        atomicAdd(&red[0], lm);
        atomicAdd(&red[1], la);
        atomicAdd(&red[2], lr);
    }
    __syncthreads();
    if (t == 0) {
        atomicAdd(&g_mid_acc, red[0] * (1.0f / 960.0f));
        atomicAdd(&g_all_acc, red[1] * (1.0f / 960.0f));
        atomicAdd(&g_rec_acc, red[2]);
    }
}

__global__ void final_kernel(const float* __restrict__ loss_diff,
                             const int* __restrict__ step,
                             const int* __restrict__ max_steps,
                             float* __restrict__ out)
{
    const float frac = 1.0f - (float)step[0] / (float)max_steps[0];
    float f2 = frac * frac;     // ^2
    float f4 = f2 * f2;         // ^4
    float f8 = f4 * f4;         // ^8
    float f10 = f8 * f2;        // ^10
    const float coeff = loss_diff[0] * f10;
    out[0] = g_mid_acc + coeff * g_all_acc + g_rec_acc * (1.0f / 196608.0f);
    // Reset accumulators for the next replay. __device__ globals are
    // zero-initialized at module load, so the first launch also sees zeros.
    g_mid_acc = 0.0f;
    g_all_acc = 0.0f;
    g_rec_acc = 0.0f;
}

extern "C" void kernel_launch(void* const* d_in, const int* in_sizes, int n_in,
                              void* d_out, int out_size)
{
    const float* inp  = (const float*)d_in[0];
    const float* outp = (const float*)d_in[1];
    const float* Wq   = (const float*)d_in[2];
    const float* Wk   = (const float*)d_in[3];
    const float* bq   = (const float*)d_in[4];
    const float* bk   = (const float*)d_in[5];
    const float* bv   = (const float*)d_in[6];
    const float* ld   = (const float*)d_in[7];
    const int*   st   = (const int*)d_in[8];
    const int*   ms   = (const int*)d_in[9];
    float* out = (float*)d_out;

    attn_loss_kernel<<<NBLK, LTOK>>>(inp, outp, Wq, Wk, bq, bk, bv, out + 1);
    final_kernel<<<1, 1>>>(ld, st, ms, out);
}

// round 8
// speedup vs baseline: 1.5147x; 1.2361x over previous
#include <cuda_runtime.h>

// Problem constants (fixed by the reference setup)
#define S1   32      // patches per image side (256/8)
#define LTOK 320     // tokens per patch problem: N * ip * ip = 5*64
#define NPAIR (LTOK/2)
#define NTHR 160     // threads per block; each thread owns queries t and t+NTHR
#define NN   5
#define IP   8
#define HH   256
#define MID  2       // N//2
#define NBLK (S1*S1) // 1024

__device__ float    g_mid_acc;
__device__ float    g_all_acc;
__device__ float    g_rec_acc;
__device__ unsigned g_done;

// ---------- f32x2 packed-math helpers (Blackwell FFMA2 path, PTX-only) ----------
typedef unsigned long long ull;

__device__ __forceinline__ ull pack2(float lo, float hi) {
    ull r;
    asm("mov.b64 %0, {%1, %2};" : "=l"(r) : "f"(lo), "f"(hi));
    return r;
}
__device__ __forceinline__ void unpack2(ull v, float& lo, float& hi) {
    asm("mov.b64 {%0, %1}, %2;" : "=f"(lo), "=f"(hi) : "l"(v));
}
__device__ __forceinline__ ull fma2(ull a, ull b, ull c) {
    ull d;
    asm("fma.rn.f32x2 %0, %1, %2, %3;" : "=l"(d) : "l"(a), "l"(b), "l"(c));
    return d;
}
__device__ __forceinline__ ull mul2(ull a, ull b) {
    ull d;
    asm("mul.rn.f32x2 %0, %1, %2;" : "=l"(d) : "l"(a), "l"(b));
    return d;
}
__device__ __forceinline__ ull add2(ull a, ull b) {
    ull d;
    asm("add.rn.f32x2 %0, %1, %2;" : "=l"(d) : "l"(a), "l"(b));
    return d;
}
__device__ __forceinline__ float ex2a(float x) {
    float y;
    asm("ex2.approx.ftz.f32 %0, %1;" : "=f"(y) : "f"(x));
    return y;
}

__global__ void __launch_bounds__(NTHR) attn_loss_kernel(
    const float* __restrict__ inp,       // (1,5,3,256,256)
    const float* __restrict__ outp,      // (1,5,3,256,256)
    const float* __restrict__ Wq,        // (3,3)
    const float* __restrict__ Wk,        // (3,3)
    const float* __restrict__ bq,        // (3,)
    const float* __restrict__ bk,        // (3,)
    const float* __restrict__ bv,        // (3,)
    const float* __restrict__ loss_diff, // scalar
    const int*   __restrict__ step,      // scalar
    const int*   __restrict__ max_steps, // scalar
    float* __restrict__ out)             // out[0]=loss, out+1 = rec_image (3*256*256)
{
    // Pair-packed SMEM layout. Pair j = tokens (2j, 2j+1).
    //   A[j] = { kx0,kx1, ky0,ky1 }
    //   B[j] = { kz0,kz1, vx0,vx1 }
    //   C[j] = { vy0,vy1, vz0,vz1 }
    __shared__ __align__(16) float A_f[NPAIR * 4];
    __shared__ __align__(16) float B_f[NPAIR * 4];
    __shared__ __align__(16) float C_f[NPAIR * 4];
    __shared__ float  outS[LTOK][3];
    __shared__ float  wp[27];            // Wq[0:9] Wk[9:18] bq[18:21] bk[21:24] bv[24:27]
    __shared__ float  red[3];            // block partials: mid, all, rec

    const int t  = threadIdx.x;
    const int r  = blockIdx.x;
    const int r1 = r >> 5;               // patch row
    const int r2 = r & 31;               // patch col

    if (t < 9)       wp[t] = Wq[t];
    else if (t < 18) wp[t] = Wk[t - 9];
    else if (t < 21) wp[t] = bq[t - 18];
    else if (t < 24) wp[t] = bk[t - 21];
    else if (t < 27) wp[t] = bv[t - 24];
    if (t == 0) { red[0] = 0.f; red[1] = 0.f; red[2] = 0.f; }
    __syncthreads();

    // ---- build q/k/v for tokens t and t+NTHR, store pair-packed to SMEM ----
    // q scaled by 1/sqrt(3) AND log2(e): scores computed in log2 domain.
    const float qs = 0.5773502691896258f * 1.4426950408889634f;
    float q0[2], q1[2], q2[2];
#pragma unroll
    for (int i = 0; i < 2; i++) {
        const int tt = t + i * NTHR;
        const int n  = tt >> 6;
        const int pp = tt & 63;
        const int h  = r1 * IP + (pp >> 3);
        const int w  = r2 * IP + (pp & 7);
        const int base = ((n * 3) * HH + h) * HH + w;
        const float x0 = inp[base];
        const float x1 = inp[base + HH * HH];
        const float x2 = inp[base + 2 * HH * HH];

        q0[i] = (wp[0] * x0 + wp[1] * x1 + wp[2] * x2 + wp[18]) * qs;
        q1[i] = (wp[3] * x0 + wp[4] * x1 + wp[5] * x2 + wp[19]) * qs;
        q2[i] = (wp[6] * x0 + wp[7] * x1 + wp[8] * x2 + wp[20]) * qs;

        const float kk0 = wp[9]  * x0 + wp[10] * x1 + wp[11] * x2 + wp[21];
        const float kk1 = wp[12] * x0 + wp[13] * x1 + wp[14] * x2 + wp[22];
        const float kk2 = wp[15] * x0 + wp[16] * x1 + wp[17] * x2 + wp[23];

        const int j = tt >> 1, o = tt & 1;
        A_f[4 * j + o]     = kk0;
        A_f[4 * j + 2 + o] = kk1;
        B_f[4 * j + o]     = kk2;
        B_f[4 * j + 2 + o] = x0 + wp[24];
        C_f[4 * j + o]     = x1 + wp[25];
        C_f[4 * j + 2 + o] = x2 + wp[26];
    }
    __syncthreads();

    // ---- streaming softmax-attention: 2 queries x 2 keys per iteration ----
    const ull qx = pack2(q0[0], q0[0]);
    const ull qy = pack2(q1[0], q1[0]);
    const ull qz = pack2(q2[0], q2[0]);
    const ull px = pack2(q0[1], q0[1]);
    const ull py = pack2(q1[1], q1[1]);
    const ull pz = pack2(q2[1], q2[1]);

    ull se2 = 0ull, a02 = 0ull, a12 = 0ull, a22 = 0ull;   // query t
    ull sf2 = 0ull, b02 = 0ull, b12 = 0ull, b22 = 0ull;   // query t+NTHR

    const ulonglong2* __restrict__ A2 = (const ulonglong2*)A_f;
    const ulonglong2* __restrict__ B2 = (const ulonglong2*)B_f;
    const ulonglong2* __restrict__ C2 = (const ulonglong2*)C_f;

#pragma unroll 4
    for (int m = 0; m < NPAIR; m++) {
        const ulonglong2 a = A2[m];                  // kx-pair, ky-pair
        const ulonglong2 b = B2[m];                  // kz-pair, vx-pair
        ull sc = mul2(qx, a.x);
        ull sd = mul2(px, a.x);
        sc = fma2(qy, a.y, sc);
        sd = fma2(py, a.y, sd);
        sc = fma2(qz, b.x, sc);
        sd = fma2(pz, b.x, sd);
        float c0, c1, d0, d1;
        unpack2(sc, c0, c1);
        unpack2(sd, d0, d1);
        const ull e = pack2(ex2a(c0), ex2a(c1));
        const ull f = pack2(ex2a(d0), ex2a(d1));
        const ulonglong2 c = C2[m];                  // vy-pair, vz-pair
        se2 = add2(se2, e);
        sf2 = add2(sf2, f);
        a02 = fma2(e, b.y, a02);
        b02 = fma2(f, b.y, b02);
        a12 = fma2(e, c.x, a12);
        b12 = fma2(f, c.x, b12);
        a22 = fma2(e, c.y, a22);
        b22 = fma2(f, c.y, b22);
    }

    {
        float sA, sB, u0, u1, v0, v1, w0, w1;
        unpack2(se2, sA, sB);
        unpack2(a02, u0, u1);
        unpack2(a12, v0, v1);
        unpack2(a22, w0, w1);
        const float inv = 1.0f / (sA + sB);
        outS[t][0] = (u0 + u1) * inv;
        outS[t][1] = (v0 + v1) * inv;
        outS[t][2] = (w0 + w1) * inv;
        unpack2(sf2, sA, sB);
        unpack2(b02, u0, u1);
        unpack2(b12, v0, v1);
        unpack2(b22, w0, w1);
        const float inv2 = 1.0f / (sA + sB);
        outS[t + NTHR][0] = (u0 + u1) * inv2;
        outS[t + NTHR][1] = (v0 + v1) * inv2;
        outS[t + NTHR][2] = (w0 + w1) * inv2;
    }
    __syncthreads();

    // ---- losses ----
    float lm = 0.f, la = 0.f, lr = 0.f;

    // all_loss / mid_loss: 960 elements (n,c,ph,pw), 6 per thread
#pragma unroll
    for (int i = 0; i < 6; i++) {
        const int e   = t + i * NTHR;
        const int n2  = e / 192;
        const int rem = e - n2 * 192;
        const int c   = rem >> 6;
        const int pp2 = rem & 63;
        const int h2  = r1 * IP + (pp2 >> 3);
        const int w2  = r2 * IP + (pp2 & 7);
        const float nin  = outp[((n2 * 3 + c) * HH + h2) * HH + w2];
        const float ninm = outp[((MID * 3 + c) * HH + h2) * HH + w2];
        const float al   = outS[n2 * 64 + pp2][c];
        const float da = nin - al;
        const float dm = ninm - al;
        la += da * da;
        lm += dm * dm;
    }

    // rec (mean over N) + rec_image write + rec_loss partial: 192 elements
    float* __restrict__ rec_out = out + 1;
#pragma unroll
    for (int i = 0; i < 2; i++) {
        const int e = t + i * NTHR;
        if (e < 192) {
            const int c   = e >> 6;
            const int pp2 = e & 63;
            const int h2  = r1 * IP + (pp2 >> 3);
            const int w2  = r2 * IP + (pp2 & 7);
            const float rec = 0.2f * (outS[pp2][c] + outS[64 + pp2][c] + outS[128 + pp2][c]
                                      + outS[192 + pp2][c] + outS[256 + pp2][c]);
            rec_out[(c * HH + h2) * HH + w2] = rec;
            const float om = outp[((MID * 3 + c) * HH + h2) * HH + w2];
            const float d  = om - rec;
            lr += d * d;
        }
    }

    // warp reduce then block reduce
#pragma unroll
    for (int o = 16; o > 0; o >>= 1) {
        lm += __shfl_down_sync(0xffffffffu, lm, o);
        la += __shfl_down_sync(0xffffffffu, la, o);
        lr += __shfl_down_sync(0xffffffffu, lr, o);
    }
    if ((t & 31) == 0) {
        atomicAdd(&red[0], lm);
        atomicAdd(&red[1], la);
        atomicAdd(&red[2], lr);
    }
    __syncthreads();

    if (t == 0) {
        atomicAdd(&g_mid_acc, red[0] * (1.0f / 960.0f));
        atomicAdd(&g_all_acc, red[1] * (1.0f / 960.0f));
        atomicAdd(&g_rec_acc, red[2]);
        __threadfence();
        const unsigned old = atomicAdd(&g_done, 1u);
        if (old == NBLK - 1) {
            // Last CTA: all accumulators visible (fence-before-increment in
            // every CTA + atomic acquire of the counter). Finalize the loss.
            const float mid = atomicAdd(&g_mid_acc, 0.0f);
            const float all = atomicAdd(&g_all_acc, 0.0f);
            const float rcc = atomicAdd(&g_rec_acc, 0.0f);
            const float frac = 1.0f - (float)step[0] / (float)max_steps[0];
            const float f2 = frac * frac;
            const float f4 = f2 * f2;
            const float f8 = f4 * f4;
            const float coeff = loss_diff[0] * (f8 * f2);   // frac^10
            out[0] = mid + coeff * all + rcc * (1.0f / 196608.0f);
            // Reset globals for the next graph replay (zero-init covers call 1).
            g_mid_acc = 0.0f;
            g_all_acc = 0.0f;
            g_rec_acc = 0.0f;
            __threadfence();
            g_done = 0u;
        }
    }
}

extern "C" void kernel_launch(void* const* d_in, const int* in_sizes, int n_in,
                              void* d_out, int out_size)
{
    const float* inp  = (const float*)d_in[0];
    const float* outp = (const float*)d_in[1];
    const float* Wq   = (const float*)d_in[2];
    const float* Wk   = (const float*)d_in[3];
    const float* bq   = (const float*)d_in[4];
    const float* bk   = (const float*)d_in[5];
    const float* bv   = (const float*)d_in[6];
    const float* ld   = (const float*)d_in[7];
    const int*   st   = (const int*)d_in[8];
    const int*   ms   = (const int*)d_in[9];
    float* out = (float*)d_out;

    attn_loss_kernel<<<NBLK, NTHR>>>(inp, outp, Wq, Wk, bq, bk, bv, ld, st, ms, out);
}